// round 1
// baseline (speedup 1.0000x reference)
#include <cuda_runtime.h>
#include <cstdint>

// Problem dims (fixed by the reference)
#define BSZ   2
#define LEN   1024
#define DM    1024
#define DI    2048
#define DS    16
#define DR    64
#define MROWS (BSZ*LEN)     // 2048

// ---------------------------------------------------------------------------
// Scratch (allocation-free: __device__ globals)
// ---------------------------------------------------------------------------
__device__ float g_xz  [MROWS * 2 * DI];   // in_proj output (x | z)
__device__ float g_x   [MROWS * DI];       // conv + silu output
__device__ float g_xdbl[MROWS * 96];       // x_proj output (dt_r | B | C)
__device__ float g_dt  [MROWS * DI];       // softplus(dt)
__device__ float g_y   [MROWS * DI];       // scan output

__device__ __forceinline__ uint32_t f2tf(float x) {
    uint32_t r;
    asm("cvt.rna.tf32.f32 %0, %1;" : "=r"(r) : "f"(x));
    return r;
}

// ---------------------------------------------------------------------------
// Generic tf32 tensor-core GEMM:  C[M,N] = A[M,K] * W[N,K]^T
// Block tile 64x64, 128 threads (4 warps of 32x32), K-step 16.
// act==1: C = softplus(C + bias[n])
// M must be a multiple of 64, K a multiple of 16 (true for all call sites).
// ---------------------------------------------------------------------------
__global__ void __launch_bounds__(128) gemm_tf32(
    const float* __restrict__ A, int lda,
    const float* __restrict__ W, int ldw,
    float* __restrict__ C, int ldc,
    int N, int K,
    const float* __restrict__ bias, int act)
{
    __shared__ uint32_t As[64][20];   // [m][k], pad 20 -> conflict-free frag reads
    __shared__ uint32_t Ws[64][20];   // [n][k]

    const int bm   = blockIdx.y * 64;
    const int bn   = blockIdx.x * 64;
    const int tid  = threadIdx.x;
    const int warp = tid >> 5;
    const int lane = tid & 31;
    const int wm   = (warp & 1) * 32;
    const int wn   = (warp >> 1) * 32;
    const int g    = lane >> 2;   // group id 0..7
    const int tg   = lane & 3;    // thread-in-group 0..3

    float acc[2][4][4];
#pragma unroll
    for (int i = 0; i < 2; i++)
#pragma unroll
        for (int j = 0; j < 4; j++)
#pragma unroll
            for (int c = 0; c < 4; c++) acc[i][j][c] = 0.f;

    for (int k0 = 0; k0 < K; k0 += 16) {
#pragma unroll
        for (int i = 0; i < 8; i++) {
            int e = tid + i * 128;       // 1024 elements per tile
            int r = e >> 4, c = e & 15;
            As[r][c] = f2tf(A[(bm + r) * lda + k0 + c]);
            int wr = bn + r;
            Ws[r][c] = f2tf(wr < N ? W[wr * ldw + k0 + c] : 0.f);
        }
        __syncthreads();

#pragma unroll
        for (int kk = 0; kk < 16; kk += 8) {
            uint32_t af[2][4], bf[4][2];
#pragma unroll
            for (int mf = 0; mf < 2; mf++) {
                int row = wm + mf * 16 + g;
                af[mf][0] = As[row][kk + tg];
                af[mf][1] = As[row + 8][kk + tg];
                af[mf][2] = As[row][kk + tg + 4];
                af[mf][3] = As[row + 8][kk + tg + 4];
            }
#pragma unroll
            for (int jf = 0; jf < 4; jf++) {
                int col = wn + jf * 8 + g;
                bf[jf][0] = Ws[col][kk + tg];
                bf[jf][1] = Ws[col][kk + tg + 4];
            }
#pragma unroll
            for (int mf = 0; mf < 2; mf++)
#pragma unroll
                for (int jf = 0; jf < 4; jf++)
                    asm volatile(
                        "mma.sync.aligned.m16n8k8.row.col.f32.tf32.tf32.f32 "
                        "{%0,%1,%2,%3},{%4,%5,%6,%7},{%8,%9},{%0,%1,%2,%3};"
                        : "+f"(acc[mf][jf][0]), "+f"(acc[mf][jf][1]),
                          "+f"(acc[mf][jf][2]), "+f"(acc[mf][jf][3])
                        : "r"(af[mf][0]), "r"(af[mf][1]),
                          "r"(af[mf][2]), "r"(af[mf][3]),
                          "r"(bf[jf][0]), "r"(bf[jf][1]));
        }
        __syncthreads();
    }

#pragma unroll
    for (int mf = 0; mf < 2; mf++)
#pragma unroll
        for (int jf = 0; jf < 4; jf++)
#pragma unroll
            for (int ci = 0; ci < 4; ci++) {
                int m  = bm + wm + mf * 16 + g + ((ci >> 1) ? 8 : 0);
                int nn = bn + wn + jf * 8 + tg * 2 + (ci & 1);
                if (nn < N) {
                    float v = acc[mf][jf][ci];
                    if (act) {
                        v += bias[nn];
                        v = (v > 20.f) ? v : log1pf(__expf(v));
                    }
                    C[m * ldc + nn] = v;
                }
            }
}

// ---------------------------------------------------------------------------
// Depthwise causal conv (K=4) + bias + SiLU.  Reads x-part of g_xz -> g_x.
// ---------------------------------------------------------------------------
__global__ void conv_silu_kernel(const float* __restrict__ xz,
                                 const float* __restrict__ w,
                                 const float* __restrict__ bias,
                                 float* __restrict__ xout)
{
    int idx = blockIdx.x * blockDim.x + threadIdx.x;   // over MROWS*DI
    int d  = idx & (DI - 1);
    int bl = idx >> 11;                                // (b*L + l)
    int l  = bl & (LEN - 1);
    float accv = bias[d];
#pragma unroll
    for (int k = 0; k < 4; k++) {
        int ll = l + k - 3;
        if (ll >= 0)
            accv += xz[(bl + (ll - l)) * (2 * DI) + d] * w[d * 4 + k];
    }
    xout[idx] = accv / (1.f + __expf(-accv));
}

// ---------------------------------------------------------------------------
// Selective scan. Block = 256 threads = 16 d-channels of one batch.
// warp: 2 d-channels x 16 states (lane = (sub, n)). Chunks of 128 steps
// staged in smem. h lives in registers across the whole sequence.
// ---------------------------------------------------------------------------
#define LC 128
__global__ void __launch_bounds__(256) scan_kernel(
    const float* __restrict__ dtp,   // g_dt
    const float* __restrict__ xp,    // g_x
    const float* __restrict__ xdbl,  // g_xdbl (B at col 64, C at col 80)
    const float* __restrict__ A_log,
    const float* __restrict__ Dp,
    float* __restrict__ y)
{
    __shared__ float sB[LC][DS];
    __shared__ float sC[LC][DS];
    __shared__ float sdt[LC][16];
    __shared__ float sx[LC][16];

    const int b   = blockIdx.x / (DI / 16);
    const int d0  = (blockIdx.x % (DI / 16)) * 16;
    const int tid = threadIdx.x;
    const int warp = tid >> 5, lane = tid & 31;
    const int sub = lane >> 4, n = lane & 15;
    const int dl  = warp * 2 + sub;      // 0..15
    const int d   = d0 + dl;

    const float a  = -__expf(A_log[d * DS + n]);
    const float Dv = Dp[d];
    float h = 0.f;

    for (int c = 0; c < LEN / LC; c++) {
        __syncthreads();
        for (int e = tid; e < LC * DS; e += 256) {
            int t = e >> 4, nn = e & 15;
            const float* row = &xdbl[(b * LEN + c * LC + t) * 96];
            sB[t][nn] = row[64 + nn];
            sC[t][nn] = row[80 + nn];
        }
        for (int e = tid; e < LC * 16; e += 256) {
            int t = e >> 4, dd = e & 15;
            int gi = (b * LEN + c * LC + t) * DI + d0 + dd;
            sdt[t][dd] = dtp[gi];
            sx[t][dd]  = xp[gi];
        }
        __syncthreads();

        for (int t = 0; t < LC; t++) {
            float dt = sdt[t][dl];
            float xv = sx[t][dl];
            float dA = __expf(dt * a);
            h = fmaf(dA, h, dt * sB[t][n] * xv);
            float part = h * sC[t][n];
            part += __shfl_xor_sync(0xffffffffu, part, 8);
            part += __shfl_xor_sync(0xffffffffu, part, 4);
            part += __shfl_xor_sync(0xffffffffu, part, 2);
            part += __shfl_xor_sync(0xffffffffu, part, 1);
            if (n == 0)
                y[(b * LEN + c * LC + t) * DI + d] = part + xv * Dv;
        }
    }
}

// ---------------------------------------------------------------------------
// Gating: y *= silu(z)
// ---------------------------------------------------------------------------
__global__ void gate_kernel(float* __restrict__ y, const float* __restrict__ xz)
{
    int idx = blockIdx.x * blockDim.x + threadIdx.x;
    int bl = idx >> 11, d = idx & (DI - 1);
    float z = xz[bl * (2 * DI) + DI + d];
    y[idx] *= z / (1.f + __expf(-z));
}

// ---------------------------------------------------------------------------
extern "C" void kernel_launch(void* const* d_in, const int* in_sizes, int n_in,
                              void* d_out, int out_size)
{
    const float* hidden = (const float*)d_in[0];
    const float* in_w   = (const float*)d_in[1];
    const float* conv_w = (const float*)d_in[2];
    const float* conv_b = (const float*)d_in[3];
    const float* xproj  = (const float*)d_in[4];
    const float* dtw    = (const float*)d_in[5];
    const float* dtb    = (const float*)d_in[6];
    const float* alog   = (const float*)d_in[7];
    const float* Dp     = (const float*)d_in[8];
    const float* outw   = (const float*)d_in[9];
    float* out = (float*)d_out;

    static float *pxz = nullptr, *px = nullptr, *pxd = nullptr,
                 *pdt = nullptr, *py = nullptr;
    if (!pxz) {
        cudaGetSymbolAddress((void**)&pxz, g_xz);
        cudaGetSymbolAddress((void**)&px,  g_x);
        cudaGetSymbolAddress((void**)&pxd, g_xdbl);
        cudaGetSymbolAddress((void**)&pdt, g_dt);
        cudaGetSymbolAddress((void**)&py,  g_y);
    }

    // 1) xz = hidden @ in_proj_w^T          (2048 x 4096 x 1024)
    gemm_tf32<<<dim3(2 * DI / 64, MROWS / 64), 128>>>(
        hidden, DM, in_w, DM, pxz, 2 * DI, 2 * DI, DM, nullptr, 0);

    // 2) x = silu(conv1d(x) + b)
    conv_silu_kernel<<<(MROWS * DI) / 256, 256>>>(pxz, conv_w, conv_b, px);

    // 3) x_dbl = x @ x_proj_w^T             (2048 x 96 x 2048)
    gemm_tf32<<<dim3(2, MROWS / 64), 128>>>(
        px, DI, xproj, DI, pxd, 96, 96, DI, nullptr, 0);

    // 4) dt = softplus(x_dbl[:, :64] @ dt_proj_w^T + b)   (2048 x 2048 x 64)
    gemm_tf32<<<dim3(DI / 64, MROWS / 64), 128>>>(
        pxd, 96, dtw, DR, pdt, DI, DI, DR, dtb, 1);

    // 5) selective scan -> y (includes + x*D)
    scan_kernel<<<BSZ * (DI / 16), 256>>>(pdt, px, pxd, alog, Dp, py);

    // 6) y *= silu(z)
    gate_kernel<<<(MROWS * DI) / 256, 256>>>(py, pxz);

    // 7) out = y @ out_proj_w^T             (2048 x 1024 x 2048)
    gemm_tf32<<<dim3(DM / 64, MROWS / 64), 128>>>(
        py, DI, outw, DI, out, DM, DM, DI, nullptr, 0);
}

// round 2
// speedup vs baseline: 1.0029x; 1.0029x over previous
#include <cuda_runtime.h>
#include <cstdint>

// Problem dims (fixed by the reference)
#define BSZ   2
#define LEN   1024
#define DM    1024
#define DI    2048
#define DS    16
#define DR    64
#define MROWS (BSZ*LEN)     // 2048

// ---------------------------------------------------------------------------
// Scratch (allocation-free: __device__ globals)
// ---------------------------------------------------------------------------
__device__ float g_xz  [MROWS * 2 * DI];   // in_proj output (x | z)
__device__ float g_x   [MROWS * DI];       // conv + silu output
__device__ float g_xdbl[MROWS * 96];       // x_proj output (dt_r | B | C)
__device__ float g_dt  [MROWS * DI];       // softplus(dt)
__device__ float g_y   [MROWS * DI];       // scan output

__device__ __forceinline__ uint32_t f2tf(float x) {
    uint32_t r;
    asm("cvt.rna.tf32.f32 %0, %1;" : "=r"(r) : "f"(x));
    return r;
}

// ---------------------------------------------------------------------------
// Generic tf32 tensor-core GEMM:  C[M,N] = A[M,K] * W[N,K]^T
// Block tile 64x64, 128 threads (4 warps of 32x32), K-step 16.
// act==1: C = softplus(C + bias[n])
// M must be a multiple of 64, K a multiple of 16 (true for all call sites).
// ---------------------------------------------------------------------------
__global__ void __launch_bounds__(128) gemm_tf32(
    const float* __restrict__ A, int lda,
    const float* __restrict__ W, int ldw,
    float* __restrict__ C, int ldc,
    int N, int K,
    const float* __restrict__ bias, int act)
{
    __shared__ uint32_t As[64][20];   // [m][k], pad 20 -> conflict-free frag reads
    __shared__ uint32_t Ws[64][20];   // [n][k]

    const int bm   = blockIdx.y * 64;
    const int bn   = blockIdx.x * 64;
    const int tid  = threadIdx.x;
    const int warp = tid >> 5;
    const int lane = tid & 31;
    const int wm   = (warp & 1) * 32;
    const int wn   = (warp >> 1) * 32;
    const int g    = lane >> 2;   // group id 0..7
    const int tg   = lane & 3;    // thread-in-group 0..3

    float acc[2][4][4];
#pragma unroll
    for (int i = 0; i < 2; i++)
#pragma unroll
        for (int j = 0; j < 4; j++)
#pragma unroll
            for (int c = 0; c < 4; c++) acc[i][j][c] = 0.f;

    for (int k0 = 0; k0 < K; k0 += 16) {
#pragma unroll
        for (int i = 0; i < 8; i++) {
            int e = tid + i * 128;       // 1024 elements per tile
            int r = e >> 4, c = e & 15;
            As[r][c] = f2tf(A[(bm + r) * lda + k0 + c]);
            int wr = bn + r;
            Ws[r][c] = f2tf(wr < N ? W[wr * ldw + k0 + c] : 0.f);
        }
        __syncthreads();

#pragma unroll
        for (int kk = 0; kk < 16; kk += 8) {
            uint32_t af[2][4], bf[4][2];
#pragma unroll
            for (int mf = 0; mf < 2; mf++) {
                int row = wm + mf * 16 + g;
                af[mf][0] = As[row][kk + tg];
                af[mf][1] = As[row + 8][kk + tg];
                af[mf][2] = As[row][kk + tg + 4];
                af[mf][3] = As[row + 8][kk + tg + 4];
            }
#pragma unroll
            for (int jf = 0; jf < 4; jf++) {
                int col = wn + jf * 8 + g;
                bf[jf][0] = Ws[col][kk + tg];
                bf[jf][1] = Ws[col][kk + tg + 4];
            }
#pragma unroll
            for (int mf = 0; mf < 2; mf++)
#pragma unroll
                for (int jf = 0; jf < 4; jf++)
                    asm volatile(
                        "mma.sync.aligned.m16n8k8.row.col.f32.tf32.tf32.f32 "
                        "{%0,%1,%2,%3},{%4,%5,%6,%7},{%8,%9},{%0,%1,%2,%3};"
                        : "+f"(acc[mf][jf][0]), "+f"(acc[mf][jf][1]),
                          "+f"(acc[mf][jf][2]), "+f"(acc[mf][jf][3])
                        : "r"(af[mf][0]), "r"(af[mf][1]),
                          "r"(af[mf][2]), "r"(af[mf][3]),
                          "r"(bf[jf][0]), "r"(bf[jf][1]));
        }
        __syncthreads();
    }

#pragma unroll
    for (int mf = 0; mf < 2; mf++)
#pragma unroll
        for (int jf = 0; jf < 4; jf++)
#pragma unroll
            for (int ci = 0; ci < 4; ci++) {
                int m  = bm + wm + mf * 16 + g + ((ci >> 1) ? 8 : 0);
                int nn = bn + wn + jf * 8 + tg * 2 + (ci & 1);
                if (nn < N) {
                    float v = acc[mf][jf][ci];
                    if (act) {
                        v += bias[nn];
                        v = (v > 20.f) ? v : log1pf(__expf(v));
                    }
                    C[m * ldc + nn] = v;
                }
            }
}

// ---------------------------------------------------------------------------
// Depthwise causal conv (K=4) + bias + SiLU.  Reads x-part of g_xz -> g_x.
// ---------------------------------------------------------------------------
__global__ void conv_silu_kernel(const float* __restrict__ xz,
                                 const float* __restrict__ w,
                                 const float* __restrict__ bias,
                                 float* __restrict__ xout)
{
    int idx = blockIdx.x * blockDim.x + threadIdx.x;   // over MROWS*DI
    int d  = idx & (DI - 1);
    int bl = idx >> 11;                                // (b*L + l)
    int l  = bl & (LEN - 1);
    float accv = bias[d];
#pragma unroll
    for (int k = 0; k < 4; k++) {
        int ll = l + k - 3;
        if (ll >= 0)
            accv += xz[(bl + (ll - l)) * (2 * DI) + d] * w[d * 4 + k];
    }
    xout[idx] = accv / (1.f + __expf(-accv));
}

// ---------------------------------------------------------------------------
// Selective scan. Block = 256 threads = 16 d-channels of one batch.
// warp: 2 d-channels x 16 states (lane = (sub, n)). Chunks of 128 steps
// staged in smem. h lives in registers across the whole sequence.
// ---------------------------------------------------------------------------
#define LC 128
__global__ void __launch_bounds__(256) scan_kernel(
    const float* __restrict__ dtp,   // g_dt
    const float* __restrict__ xp,    // g_x
    const float* __restrict__ xdbl,  // g_xdbl (B at col 64, C at col 80)
    const float* __restrict__ A_log,
    const float* __restrict__ Dp,
    float* __restrict__ y)
{
    __shared__ float sB[LC][DS];
    __shared__ float sC[LC][DS];
    __shared__ float sdt[LC][16];
    __shared__ float sx[LC][16];

    const int b   = blockIdx.x / (DI / 16);
    const int d0  = (blockIdx.x % (DI / 16)) * 16;
    const int tid = threadIdx.x;
    const int warp = tid >> 5, lane = tid & 31;
    const int sub = lane >> 4, n = lane & 15;
    const int dl  = warp * 2 + sub;      // 0..15
    const int d   = d0 + dl;

    const float a  = -__expf(A_log[d * DS + n]);
    const float Dv = Dp[d];
    float h = 0.f;

    for (int c = 0; c < LEN / LC; c++) {
        __syncthreads();
        for (int e = tid; e < LC * DS; e += 256) {
            int t = e >> 4, nn = e & 15;
            const float* row = &xdbl[(b * LEN + c * LC + t) * 96];
            sB[t][nn] = row[64 + nn];
            sC[t][nn] = row[80 + nn];
        }
        for (int e = tid; e < LC * 16; e += 256) {
            int t = e >> 4, dd = e & 15;
            int gi = (b * LEN + c * LC + t) * DI + d0 + dd;
            sdt[t][dd] = dtp[gi];
            sx[t][dd]  = xp[gi];
        }
        __syncthreads();

        for (int t = 0; t < LC; t++) {
            float dt = sdt[t][dl];
            float xv = sx[t][dl];
            float dA = __expf(dt * a);
            h = fmaf(dA, h, dt * sB[t][n] * xv);
            float part = h * sC[t][n];
            part += __shfl_xor_sync(0xffffffffu, part, 8);
            part += __shfl_xor_sync(0xffffffffu, part, 4);
            part += __shfl_xor_sync(0xffffffffu, part, 2);
            part += __shfl_xor_sync(0xffffffffu, part, 1);
            if (n == 0)
                y[(b * LEN + c * LC + t) * DI + d] = part + xv * Dv;
        }
    }
}

// ---------------------------------------------------------------------------
// Gating: y *= silu(z)
// ---------------------------------------------------------------------------
__global__ void gate_kernel(float* __restrict__ y, const float* __restrict__ xz)
{
    int idx = blockIdx.x * blockDim.x + threadIdx.x;
    int bl = idx >> 11, d = idx & (DI - 1);
    float z = xz[bl * (2 * DI) + DI + d];
    y[idx] *= z / (1.f + __expf(-z));
}

// ---------------------------------------------------------------------------
extern "C" void kernel_launch(void* const* d_in, const int* in_sizes, int n_in,
                              void* d_out, int out_size)
{
    const float* hidden = (const float*)d_in[0];
    const float* in_w   = (const float*)d_in[1];
    const float* conv_w = (const float*)d_in[2];
    const float* conv_b = (const float*)d_in[3];
    const float* xproj  = (const float*)d_in[4];
    const float* dtw    = (const float*)d_in[5];
    const float* dtb    = (const float*)d_in[6];
    const float* alog   = (const float*)d_in[7];
    const float* Dp     = (const float*)d_in[8];
    const float* outw   = (const float*)d_in[9];
    float* out = (float*)d_out;

    static float *pxz = nullptr, *px = nullptr, *pxd = nullptr,
                 *pdt = nullptr, *py = nullptr;
    if (!pxz) {
        cudaGetSymbolAddress((void**)&pxz, g_xz);
        cudaGetSymbolAddress((void**)&px,  g_x);
        cudaGetSymbolAddress((void**)&pxd, g_xdbl);
        cudaGetSymbolAddress((void**)&pdt, g_dt);
        cudaGetSymbolAddress((void**)&py,  g_y);
    }

    // 1) xz = hidden @ in_proj_w^T          (2048 x 4096 x 1024)
    gemm_tf32<<<dim3(2 * DI / 64, MROWS / 64), 128>>>(
        hidden, DM, in_w, DM, pxz, 2 * DI, 2 * DI, DM, nullptr, 0);

    // 2) x = silu(conv1d(x) + b)
    conv_silu_kernel<<<(MROWS * DI) / 256, 256>>>(pxz, conv_w, conv_b, px);

    // 3) x_dbl = x @ x_proj_w^T             (2048 x 96 x 2048)
    gemm_tf32<<<dim3(2, MROWS / 64), 128>>>(
        px, DI, xproj, DI, pxd, 96, 96, DI, nullptr, 0);

    // 4) dt = softplus(x_dbl[:, :64] @ dt_proj_w^T + b)   (2048 x 2048 x 64)
    gemm_tf32<<<dim3(DI / 64, MROWS / 64), 128>>>(
        pxd, 96, dtw, DR, pdt, DI, DI, DR, dtb, 1);

    // 5) selective scan -> y (includes + x*D)
    scan_kernel<<<BSZ * (DI / 16), 256>>>(pdt, px, pxd, alog, Dp, py);

    // 6) y *= silu(z)
    gate_kernel<<<(MROWS * DI) / 256, 256>>>(py, pxz);

    // 7) out = y @ out_proj_w^T             (2048 x 1024 x 2048)
    gemm_tf32<<<dim3(DM / 64, MROWS / 64), 128>>>(
        py, DI, outw, DI, out, DM, DM, DI, nullptr, 0);
}